// round 8
// baseline (speedup 1.0000x reference)
#include <cuda_runtime.h>
#include <cstdint>
#include <math.h>

// Problem constants
#define BB 8
#define CC 128
#define HH 8
#define FFN 512
#define PP 1024            // L*F positions per batch
#define NTOK 8192          // B*P tokens
#define CH 1024            // C*H

// ---------------------------------------------------------------------------
// Scratch
// ---------------------------------------------------------------------------
#define OFF_Q   0L
#define SZ_QKV  (8L * 8 * 1024 * 128)
#define OFF_K   (OFF_Q + SZ_QKV)
#define OFF_V   (OFF_K + SZ_QKV)           // V stored TRANSPOSED: (bh, c, p)
#define OFF_S   (OFF_V + SZ_QKV)
#define SZ_S    (64L * 1024 * 1024)
#define OFF_ZC  (OFF_S + SZ_S)
#define SZ_ZC   (8192L * 1024)
#define OFF_AO  (OFF_ZC + SZ_ZC)
#define SZ_TOK  (8192L * 128)
#define OFF_Z1  (OFF_AO + SZ_TOK)
#define OFF_H1  (OFF_Z1 + SZ_TOK)
#define SZ_H1   (8192L * 512)
#define OFF_FFY (OFF_H1 + SZ_H1)
#define SCRATCH_TOTAL (OFF_FFY + SZ_TOK)

__device__ float g_scratch[SCRATCH_TOTAL];

// ---------------------------------------------------------------------------
// PTX helpers
// ---------------------------------------------------------------------------
__device__ __forceinline__ void mma_tf32(
    float& c0, float& c1, float& c2, float& c3,
    uint32_t a0, uint32_t a1, uint32_t a2, uint32_t a3,
    uint32_t b0, uint32_t b1)
{
    asm volatile(
        "mma.sync.aligned.m16n8k8.row.col.f32.tf32.tf32.f32 "
        "{%0,%1,%2,%3}, {%4,%5,%6,%7}, {%8,%9}, {%0,%1,%2,%3};"
        : "+f"(c0), "+f"(c1), "+f"(c2), "+f"(c3)
        : "r"(a0), "r"(a1), "r"(a2), "r"(a3), "r"(b0), "r"(b1));
}

__device__ __forceinline__ uint32_t smem_u32(const void* p) {
    uint32_t a;
    asm("{ .reg .u64 t; cvta.to.shared.u64 t, %1; cvt.u32.u64 %0, t; }" : "=r"(a) : "l"(p));
    return a;
}
__device__ __forceinline__ void cp16(uint32_t dst, const void* src) {
    asm volatile("cp.async.cg.shared.global [%0], [%1], 16;" :: "r"(dst), "l"(src));
}
__device__ __forceinline__ void cp_commit() {
    asm volatile("cp.async.commit_group;" ::: "memory");
}
template<int N>
__device__ __forceinline__ void cp_wait() {
    asm volatile("cp.async.wait_group %0;" :: "n"(N) : "memory");
}

// ===========================================================================
// Generic TF32 tensor-core GEMM (unchanged from R7 winner)
// ===========================================================================
#define STAGES 3
#define STAGE_BYTES 32768
#define BTILE_OFF 16384
#define SMEM_BYTES (STAGES * STAGE_BYTES)

template<int OUTMAP, bool RELU>
__global__ __launch_bounds__(256, 2) void tgemm(
    const float* __restrict__ A, int lda, long sA,
    const float* __restrict__ Bm, int ldb, long sB,
    const float* __restrict__ bias,
    float* __restrict__ Co, int ldc, long sC,
    int K, float scale)
{
    extern __shared__ float sm[];
    const uint32_t sbase = smem_u32(sm);

    const int t   = threadIdx.x;
    const int wid = t >> 5;
    const int lid = t & 31;
    const int g   = lid >> 2;
    const int t4  = lid & 3;
    const int wm  = wid & 3;
    const int wn  = wid >> 2;

    const int bz = blockIdx.z;
    const int m0 = blockIdx.y << 7;
    const int n0 = blockIdx.x << 7;
    A  += (long)bz * sA;
    Bm += (long)bz * sB;

    const int r_ld  = t >> 3;
    const int c4_ld = t & 7;

    auto issue_stage = [&](int c, int s) {
        const int k0 = c << 5;
        const uint32_t stage = sbase + s * STAGE_BYTES;
#pragma unroll
        for (int i = 0; i < 4; i++) {
            const int r  = r_ld + i * 32;
            const uint32_t doff = (uint32_t)(r << 7) + (uint32_t)((c4_ld ^ (r & 7)) << 4);
            cp16(stage + doff,              A  + (long)(m0 + r) * lda + k0 + (c4_ld << 2));
            cp16(stage + BTILE_OFF + doff,  Bm + (long)(n0 + r) * ldb + k0 + (c4_ld << 2));
        }
        cp_commit();
    };

    float acc[2][8][4];
#pragma unroll
    for (int mt = 0; mt < 2; mt++)
#pragma unroll
        for (int nt = 0; nt < 8; nt++)
#pragma unroll
            for (int i = 0; i < 4; i++) acc[mt][nt][i] = 0.f;

    const int nch = K >> 5;

#pragma unroll
    for (int c = 0; c < STAGES - 1; c++)
        if (c < nch) issue_stage(c, c);

    for (int c = 0; c < nch; c++) {
        const int s = c % STAGES;
        cp_wait<STAGES - 2>();
        __syncthreads();

        if (c + STAGES - 1 < nch) issue_stage(c + STAGES - 1, (c + STAGES - 1) % STAGES);

        const float* Ab = sm + s * (STAGE_BYTES / 4);
        const float* Bb = Ab + (BTILE_OFF / 4);

#pragma unroll
        for (int kk = 0; kk < 4; kk++) {
            const int u0 = (2 * kk) ^ g;
            const int u1 = u0 ^ 1;
            uint32_t af[2][4];
#pragma unroll
            for (int mt = 0; mt < 2; mt++) {
                const int ra = wm * 32 + mt * 16 + g;
                af[mt][0] = __float_as_uint(Ab[(ra)     * 32 + u0 * 4 + t4]);
                af[mt][1] = __float_as_uint(Ab[(ra + 8) * 32 + u0 * 4 + t4]);
                af[mt][2] = __float_as_uint(Ab[(ra)     * 32 + u1 * 4 + t4]);
                af[mt][3] = __float_as_uint(Ab[(ra + 8) * 32 + u1 * 4 + t4]);
            }
#pragma unroll
            for (int nt = 0; nt < 8; nt++) {
                const int rb = wn * 64 + nt * 8 + g;
                uint32_t b0 = __float_as_uint(Bb[rb * 32 + u0 * 4 + t4]);
                uint32_t b1 = __float_as_uint(Bb[rb * 32 + u1 * 4 + t4]);
#pragma unroll
                for (int mt = 0; mt < 2; mt++)
                    mma_tf32(acc[mt][nt][0], acc[mt][nt][1], acc[mt][nt][2], acc[mt][nt][3],
                             af[mt][0], af[mt][1], af[mt][2], af[mt][3], b0, b1);
            }
        }
        __syncthreads();
    }

    auto outoff = [&](int m, int n) -> long {
        if constexpr (OUTMAP == 0) {
            return (long)bz * sC + (long)m * ldc + n;
        } else if constexpr (OUTMAP == 1) {
            int b = m >> 10, p = m & 1023;
            int cq = n >> 3, h = n & 7;
            return (((long)(b * HH + h) * PP + p) << 7) + cq;
        } else {
            int b = m >> 10, p = m & 1023;
            int cq = n >> 3, h = n & 7;
            return (((long)(b * HH + h) * CC + cq) << 10) + p;
        }
    };

#pragma unroll
    for (int mt = 0; mt < 2; mt++) {
        const int r0 = m0 + wm * 32 + mt * 16 + g;
#pragma unroll
        for (int nt = 0; nt < 8; nt++) {
            const int col = n0 + wn * 64 + nt * 8 + t4 * 2;
            float v0 = acc[mt][nt][0] * scale;
            float v1 = acc[mt][nt][1] * scale;
            float v2 = acc[mt][nt][2] * scale;
            float v3 = acc[mt][nt][3] * scale;
            if (bias) {
                float bi0 = bias[col], bi1 = bias[col + 1];
                v0 += bi0; v1 += bi1; v2 += bi0; v3 += bi1;
            }
            if (RELU) {
                v0 = fmaxf(v0, 0.f); v1 = fmaxf(v1, 0.f);
                v2 = fmaxf(v2, 0.f); v3 = fmaxf(v3, 0.f);
            }
            if constexpr (OUTMAP == 0) {
                *(float2*)(Co + outoff(r0, col))     = make_float2(v0, v1);
                *(float2*)(Co + outoff(r0 + 8, col)) = make_float2(v2, v3);
            } else {
                Co[outoff(r0, col)]         = v0;
                Co[outoff(r0, col + 1)]     = v1;
                Co[outoff(r0 + 8, col)]     = v2;
                Co[outoff(r0 + 8, col + 1)] = v3;
            }
        }
    }
}

// ===========================================================================
// Fused double-softmax + AV kernel.
// CTA = (q-tile of 32 rows, bh). S tile (32x1024 fp32) -> SMEM, softmax in
// place, then Z(32x128) = A @ Vt^T with V streamed (double-buffered chunks).
// ===========================================================================
#define AQS 1028                       // A row stride (floats): 1028%32=4 -> bank 4g+t4
#define VBS 68                         // V row stride (floats): 68%32=4
#define VCHUNK_F (128 * VBS)           // one V chunk buffer (128 c-rows x 64 p)
#define FSMEM_FLOATS (32 * AQS + 2 * VCHUNK_F)
#define FSMEM_BYTES (FSMEM_FLOATS * 4) // 131584 + 69632 = 201216

__global__ __launch_bounds__(256, 1) void softmax_av_kernel(
    const float* __restrict__ S, const float* __restrict__ Vt,
    float* __restrict__ zc)
{
    extern __shared__ float sm[];
    float* Abuf = sm;
    const uint32_t sbase = smem_u32(sm);
    const uint32_t vbase = sbase + 32 * AQS * 4;

    const int t   = threadIdx.x;
    const int wid = t >> 5;
    const int lid = t & 31;
    const int bh  = blockIdx.y;
    const int q0  = blockIdx.x << 5;

    const float* Srow = S + ((long)bh * PP + q0) * PP;
    const float* Vb   = Vt + (long)bh * CC * PP;

    // ---- issue S tile load (32 x 1024 fp32) ----
#pragma unroll
    for (int i = 0; i < 32; i++) {
        int u  = i * 256 + t;          // 0..8191
        int r  = u >> 8;               // q row
        int k4 = u & 255;              // float4 col
        cp16(sbase + (uint32_t)(r * AQS + k4 * 4) * 4, Srow + (long)r * PP + k4 * 4);
    }
    cp_commit();

    // ---- issue V chunk 0 load (overlaps with softmax below) ----
    auto load_vchunk = [&](int ch, int buf) {
#pragma unroll
        for (int i = 0; i < 8; i++) {
            int u  = i * 256 + t;      // 0..2047
            int c  = u >> 4;           // c row 0..127
            int p4 = u & 15;           // float4 within 64-col chunk
            cp16(vbase + (uint32_t)(buf * VCHUNK_F + c * VBS + p4 * 4) * 4,
                 Vb + (long)c * PP + ch * 64 + p4 * 4);
        }
        cp_commit();
    };
    load_vchunk(0, 0);

    cp_wait<1>();     // S tile complete (V0 may still be in flight)
    __syncthreads();

    // ---- double softmax, one warp per row, 4 rounds ----
    for (int it = 0; it < 4; it++) {
        const int row = it * 8 + wid;
        float* rp = Abuf + row * AQS;

        // phase 1: softmax over m (64) for each g (16). lane: g=lid&15, half=lid>>4
        const int gg = lid & 15;
        const int mb = (lid >> 4) * 32;
        float mx = -1e30f;
#pragma unroll
        for (int mm = 0; mm < 32; mm++) mx = fmaxf(mx, rp[(mb + mm) * 16 + gg]);
        mx = fmaxf(mx, __shfl_xor_sync(0xffffffffu, mx, 16));
        float sum = 0.f;
#pragma unroll
        for (int mm = 0; mm < 32; mm++) {
            float e = __expf(rp[(mb + mm) * 16 + gg] - mx);
            rp[(mb + mm) * 16 + gg] = e;
            sum += e;
        }
        sum += __shfl_xor_sync(0xffffffffu, sum, 16);
        float inv = 1.f / sum;
#pragma unroll
        for (int mm = 0; mm < 32; mm++) rp[(mb + mm) * 16 + gg] *= inv;
        __syncwarp();

        // phase 2: softmax over g (16) per m; lane handles m = 2*lid, 2*lid+1
        // (rotated g index to avoid 32-way bank conflicts)
#pragma unroll
        for (int r2 = 0; r2 < 2; r2++) {
            float* mp = rp + ((lid << 1) + r2) * 16;
            float mx2 = -1e30f;
#pragma unroll
            for (int j = 0; j < 16; j++) mx2 = fmaxf(mx2, mp[(j + lid) & 15]);
            float s2 = 0.f;
#pragma unroll
            for (int j = 0; j < 16; j++) {
                int idx = (j + lid) & 15;
                float e = __expf(mp[idx] - mx2);
                mp[idx] = e;
                s2 += e;
            }
            float i2 = 1.f / s2;
#pragma unroll
            for (int j = 0; j < 16; j++) mp[(j + lid) & 15] *= i2;
        }
        __syncwarp();
    }
    __syncthreads();

    // ---- AV: Z(32x128) = A(32x1024) @ Vt^T, 16 chunks of k=64 ----
    const int g  = lid >> 2;
    const int t4 = lid & 3;
    const int wm = wid & 1;        // 16 q rows
    const int wn = wid >> 1;       // 32 c cols

    float acc[4][4];
#pragma unroll
    for (int nt = 0; nt < 4; nt++)
#pragma unroll
        for (int i = 0; i < 4; i++) acc[nt][i] = 0.f;

    for (int ch = 0; ch < 16; ch++) {
        const int buf = ch & 1;
        if (ch + 1 < 16) load_vchunk(ch + 1, buf ^ 1);
        if (ch + 1 < 16) cp_wait<1>(); else cp_wait<0>();
        __syncthreads();

        const float* Vc = sm + 32 * AQS + buf * VCHUNK_F;
#pragma unroll
        for (int kk = 0; kk < 8; kk++) {
            const int kg = ch * 64 + kk * 8 + t4;     // global k for A
            const int kl = kk * 8 + t4;               // local k for V
            const int ra = wm * 16 + g;
            uint32_t a0 = __float_as_uint(Abuf[(ra)     * AQS + kg]);
            uint32_t a1 = __float_as_uint(Abuf[(ra + 8) * AQS + kg]);
            uint32_t a2 = __float_as_uint(Abuf[(ra)     * AQS + kg + 4]);
            uint32_t a3 = __float_as_uint(Abuf[(ra + 8) * AQS + kg + 4]);
#pragma unroll
            for (int nt = 0; nt < 4; nt++) {
                const int rb = wn * 32 + nt * 8 + g;
                uint32_t b0 = __float_as_uint(Vc[rb * VBS + kl]);
                uint32_t b1 = __float_as_uint(Vc[rb * VBS + kl + 4]);
                mma_tf32(acc[nt][0], acc[nt][1], acc[nt][2], acc[nt][3],
                         a0, a1, a2, a3, b0, b1);
            }
        }
        __syncthreads();
    }

    // ---- epilogue: head-recombine into zc[(b*P+p)*1024 + c*8 + h] ----
    const int b = bh >> 3, h = bh & 7;
    const int p0 = q0 + wm * 16 + g;
#pragma unroll
    for (int nt = 0; nt < 4; nt++) {
        const int col = wn * 32 + nt * 8 + t4 * 2;
        zc[((long)(b * PP + p0) << 10) + (col << 3) + h]           = acc[nt][0];
        zc[((long)(b * PP + p0) << 10) + ((col + 1) << 3) + h]     = acc[nt][1];
        zc[((long)(b * PP + p0 + 8) << 10) + (col << 3) + h]       = acc[nt][2];
        zc[((long)(b * PP + p0 + 8) << 10) + ((col + 1) << 3) + h] = acc[nt][3];
    }
}

// ---------------------------------------------------------------------------
// out = LayerNorm(A + R) * gamma + beta
// ---------------------------------------------------------------------------
__global__ __launch_bounds__(128) void add_ln_kernel(
    const float* __restrict__ A, const float* __restrict__ R,
    const float* __restrict__ gam, const float* __restrict__ bet,
    float* __restrict__ out)
{
    const long base = (long)blockIdx.x * CC;
    const int t = threadIdx.x;
    __shared__ float red[8];

    float v = A[base + t] + R[base + t];

    float s = v;
#pragma unroll
    for (int o = 16; o; o >>= 1) s += __shfl_xor_sync(0xffffffffu, s, o);
    if ((t & 31) == 0) red[t >> 5] = s;
    __syncthreads();
    const float mean = (red[0] + red[1] + red[2] + red[3]) * (1.f / CC);

    const float d = v - mean;
    float s2 = d * d;
#pragma unroll
    for (int o = 16; o; o >>= 1) s2 += __shfl_xor_sync(0xffffffffu, s2, o);
    if ((t & 31) == 0) red[4 + (t >> 5)] = s2;
    __syncthreads();
    const float var = (red[4] + red[5] + red[6] + red[7]) * (1.f / CC);

    out[base + t] = d * rsqrtf(var + 1e-5f) * gam[t] + bet[t];
}

// ---------------------------------------------------------------------------
extern "C" void kernel_launch(void* const* d_in, const int* in_sizes, int n_in,
                              void* d_out, int out_size)
{
    const float* x     = (const float*)d_in[0];
    const float* wq    = (const float*)d_in[1];
    const float* bq    = (const float*)d_in[2];
    const float* wk    = (const float*)d_in[3];
    const float* bk    = (const float*)d_in[4];
    const float* wv    = (const float*)d_in[5];
    const float* bv    = (const float*)d_in[6];
    const float* wo    = (const float*)d_in[7];
    const float* bo    = (const float*)d_in[8];
    const float* ln1_g = (const float*)d_in[9];
    const float* ln1_b = (const float*)d_in[10];
    const float* w1    = (const float*)d_in[11];
    const float* b1    = (const float*)d_in[12];
    const float* w2    = (const float*)d_in[13];
    const float* b2    = (const float*)d_in[14];
    const float* ln2_g = (const float*)d_in[15];
    const float* ln2_b = (const float*)d_in[16];
    float* out = (float*)d_out;

    float* scr = nullptr;
    cudaGetSymbolAddress((void**)&scr, g_scratch);
    float* q   = scr + OFF_Q;
    float* k   = scr + OFF_K;
    float* vt  = scr + OFF_V;
    float* sS  = scr + OFF_S;
    float* zc  = scr + OFF_ZC;
    float* ao  = scr + OFF_AO;
    float* z1  = scr + OFF_Z1;
    float* h1  = scr + OFF_H1;
    float* ffy = scr + OFF_FFY;

    cudaFuncSetAttribute(tgemm<0, false>, cudaFuncAttributeMaxDynamicSharedMemorySize, SMEM_BYTES);
    cudaFuncSetAttribute(tgemm<0, true>,  cudaFuncAttributeMaxDynamicSharedMemorySize, SMEM_BYTES);
    cudaFuncSetAttribute(tgemm<1, false>, cudaFuncAttributeMaxDynamicSharedMemorySize, SMEM_BYTES);
    cudaFuncSetAttribute(tgemm<3, false>, cudaFuncAttributeMaxDynamicSharedMemorySize, SMEM_BYTES);
    cudaFuncSetAttribute(softmax_av_kernel, cudaFuncAttributeMaxDynamicSharedMemorySize, FSMEM_BYTES);

    const float inv_sqrt_c = 0.08838834764831845f;

    // 1-3: QKV projections (8192 x 1024 x 128)
    tgemm<1, false><<<dim3(8, 64, 1), 256, SMEM_BYTES>>>(
        x, CC, 0, wq, CC, 0, bq, q, 0, 0, CC, 1.f);
    tgemm<1, false><<<dim3(8, 64, 1), 256, SMEM_BYTES>>>(
        x, CC, 0, wk, CC, 0, bk, k, 0, 0, CC, 1.f);
    tgemm<3, false><<<dim3(8, 64, 1), 256, SMEM_BYTES>>>(
        x, CC, 0, wv, CC, 0, bv, vt, 0, 0, CC, 1.f);

    // 4: scores = Q @ K^T / sqrt(C)  (64 batches of 1024x1024x128)
    tgemm<0, false><<<dim3(8, 8, 64), 256, SMEM_BYTES>>>(
        q, CC, (long)PP * CC, k, CC, (long)PP * CC, nullptr,
        sS, PP, (long)PP * PP, CC, inv_sqrt_c);

    // 5: fused double-softmax + AV -> zc (head-recombined)
    softmax_av_kernel<<<dim3(32, 64), 256, FSMEM_BYTES>>>(sS, vt, zc);

    // 6: attn_out = zc @ wo^T + bo  (8192x128x1024)
    tgemm<0, false><<<dim3(1, 64, 1), 256, SMEM_BYTES>>>(
        zc, CH, 0, wo, CH, 0, bo, ao, CC, 0, CH, 1.f);

    // 7: z1 = LN1(attn_out + x)
    add_ln_kernel<<<NTOK, 128>>>(ao, x, ln1_g, ln1_b, z1);

    // 8: h1 = relu(z1 @ w1^T + b1)  (8192x512x128)
    tgemm<0, true><<<dim3(4, 64, 1), 256, SMEM_BYTES>>>(
        z1, CC, 0, w1, CC, 0, b1, h1, FFN, 0, CC, 1.f);

    // 9: ffy = h1 @ w2^T + b2  (8192x128x512)
    tgemm<0, false><<<dim3(1, 64, 1), 256, SMEM_BYTES>>>(
        h1, FFN, 0, w2, FFN, 0, b2, ffy, CC, 0, FFN, 1.f);

    // 10: out = LN2(ffy + z1)
    add_ln_kernel<<<NTOK, 128>>>(ffy, z1, ln2_g, ln2_b, out);
}

// round 11
// speedup vs baseline: 1.3460x; 1.3460x over previous
#include <cuda_runtime.h>
#include <cstdint>
#include <math.h>

// Problem constants
#define BB 8
#define CC 128
#define HH 8
#define FFN 512
#define PP 1024            // L*F positions per batch
#define NTOK 8192          // B*P tokens
#define CH 1024            // C*H

// ---------------------------------------------------------------------------
// Scratch
// ---------------------------------------------------------------------------
#define OFF_Q   0L
#define SZ_QKV  (8L * 8 * 1024 * 128)
#define OFF_K   (OFF_Q + SZ_QKV)
#define OFF_V   (OFF_K + SZ_QKV)           // V stored TRANSPOSED: (bh, c, p)
#define OFF_S   (OFF_V + SZ_QKV)
#define SZ_S    (64L * 1024 * 1024)
#define OFF_ZC  (OFF_S + SZ_S)
#define SZ_ZC   (8192L * 1024)
#define OFF_AO  (OFF_ZC + SZ_ZC)
#define SZ_TOK  (8192L * 128)
#define OFF_Z1  (OFF_AO + SZ_TOK)
#define OFF_H1  (OFF_Z1 + SZ_TOK)
#define SZ_H1   (8192L * 512)
#define OFF_FFY (OFF_H1 + SZ_H1)
#define OFF_PS  (OFF_FFY + SZ_TOK)
#define SZ_PS   (64L * 8 * 1024 * 16)      // [bh][ntile][row][g] partial exp-sums
#define SCRATCH_TOTAL (OFF_PS + SZ_PS)

__device__ float g_scratch[SCRATCH_TOTAL];

// ---------------------------------------------------------------------------
// PTX helpers
// ---------------------------------------------------------------------------
__device__ __forceinline__ void mma_tf32(
    float& c0, float& c1, float& c2, float& c3,
    uint32_t a0, uint32_t a1, uint32_t a2, uint32_t a3,
    uint32_t b0, uint32_t b1)
{
    asm volatile(
        "mma.sync.aligned.m16n8k8.row.col.f32.tf32.tf32.f32 "
        "{%0,%1,%2,%3}, {%4,%5,%6,%7}, {%8,%9}, {%0,%1,%2,%3};"
        : "+f"(c0), "+f"(c1), "+f"(c2), "+f"(c3)
        : "r"(a0), "r"(a1), "r"(a2), "r"(a3), "r"(b0), "r"(b1));
}

__device__ __forceinline__ uint32_t smem_u32(const void* p) {
    uint32_t a;
    asm("{ .reg .u64 t; cvta.to.shared.u64 t, %1; cvt.u32.u64 %0, t; }" : "=r"(a) : "l"(p));
    return a;
}
__device__ __forceinline__ void cp16(uint32_t dst, const void* src) {
    asm volatile("cp.async.cg.shared.global [%0], [%1], 16;" :: "r"(dst), "l"(src));
}
__device__ __forceinline__ void cp_commit() {
    asm volatile("cp.async.commit_group;" ::: "memory");
}
template<int N>
__device__ __forceinline__ void cp_wait() {
    asm volatile("cp.async.wait_group %0;" :: "n"(N) : "memory");
}

// ===========================================================================
// TF32 tensor-core GEMM, 128x128 tile, cp.async 3-stage pipeline.
// EPI: 0 = normal (scale/bias/relu, OUTMAP store)
//      1 = scores: e = exp(scale*acc), coalesced store + per-CTA partial sums
//          over key-L into PS[bh][ntile][row][g]
// SMAXA: A operand is the e-tensor; apply double-softmax normalization to
//        each A chunk in smem before the mma (p1 = e*inv_sum1; p2 = softmax_g(p1)).
// ===========================================================================
#define STAGES 3
#define STAGE_BYTES 32768
#define BTILE_OFF 16384
#define SMEM_BYTES (STAGES * STAGE_BYTES)              // 98304
#define SMEM_AV_BYTES (SMEM_BYTES + 8192)              // + invs[128][16]

template<int OUTMAP, bool RELU, int EPI, bool SMAXA>
__global__ __launch_bounds__(256, 2) void tgemm(
    const float* __restrict__ A, int lda, long sA,
    const float* __restrict__ Bm, int ldb, long sB,
    const float* __restrict__ bias,
    float* __restrict__ Co, int ldc, long sC,
    int K, float scale, float* __restrict__ PS)
{
    extern __shared__ float sm[];
    const uint32_t sbase = smem_u32(sm);

    const int t   = threadIdx.x;
    const int wid = t >> 5;
    const int lid = t & 31;
    const int g   = lid >> 2;
    const int t4  = lid & 3;
    const int wm  = wid & 3;
    const int wn  = wid >> 2;

    const int bz = blockIdx.z;
    const int m0 = blockIdx.y << 7;
    const int n0 = blockIdx.x << 7;
    A  += (long)bz * sA;
    Bm += (long)bz * sB;

    const int r_ld  = t >> 3;
    const int c4_ld = t & 7;

    auto issue_stage = [&](int c, int s) {
        const int k0 = c << 5;
        const uint32_t stage = sbase + s * STAGE_BYTES;
#pragma unroll
        for (int i = 0; i < 4; i++) {
            const int r  = r_ld + i * 32;
            const uint32_t doff = (uint32_t)(r << 7) + (uint32_t)((c4_ld ^ (r & 7)) << 4);
            cp16(stage + doff,              A  + (long)(m0 + r) * lda + k0 + (c4_ld << 2));
            cp16(stage + BTILE_OFF + doff,  Bm + (long)(n0 + r) * ldb + k0 + (c4_ld << 2));
        }
        cp_commit();
    };

    float acc[2][8][4];
#pragma unroll
    for (int mt = 0; mt < 2; mt++)
#pragma unroll
        for (int nt = 0; nt < 8; nt++)
#pragma unroll
            for (int i = 0; i < 4; i++) acc[mt][nt][i] = 0.f;

    const int nch = K >> 5;

#pragma unroll
    for (int c = 0; c < STAGES - 1; c++)
        if (c < nch) issue_stage(c, c);

    // ---- SMAXA: build inv_sum1[row][g] from 8 deterministic partials ----
    float* invs = sm + (SMEM_BYTES / 4);
    if constexpr (SMAXA) {
#pragma unroll
        for (int i = 0; i < 8; i++) {
            const int pr = i * 256 + t;          // 0..2047
            const int lr = pr >> 4, gg = pr & 15;
            float s1 = 0.f;
#pragma unroll
            for (int nx = 0; nx < 8; nx++)
                s1 += PS[((long)(bz * 8 + nx) * PP + m0 + lr) * 16 + gg];
            invs[lr * 16 + gg] = 1.0f / s1;
        }
        __syncthreads();
    }

    for (int c = 0; c < nch; c++) {
        const int s = c % STAGES;
        cp_wait<STAGES - 2>();
        __syncthreads();

        if (c + STAGES - 1 < nch) issue_stage(c + STAGES - 1, (c + STAGES - 1) % STAGES);

        float* Ab = sm + s * (STAGE_BYTES / 4);
        const float* Bb = Ab + (BTILE_OFF / 4);

        if constexpr (SMAXA) {
            // in-place double-softmax normalization of this 128x32 e-chunk.
            // thread t: row r = t>>1, half m2 = t&1 -> one 16-g group.
            const int r  = t >> 1;
            const int m2 = t & 1;
            const int rx = r & 7;
            float z = 0.f;
#pragma unroll
            for (int q = 0; q < 4; q++) {
                const int u = (m2 * 4 + q) ^ rx;
                float4 e4 = *(float4*)(Ab + r * 32 + u * 4);
                float4 iv = *(float4*)(invs + r * 16 + q * 4);
                float w0 = __expf(e4.x * iv.x);
                float w1 = __expf(e4.y * iv.y);
                float w2 = __expf(e4.z * iv.z);
                float w3 = __expf(e4.w * iv.w);
                z += (w0 + w1) + (w2 + w3);
                *(float4*)(Ab + r * 32 + u * 4) = make_float4(w0, w1, w2, w3);
            }
            const float rz = 1.0f / z;
#pragma unroll
            for (int q = 0; q < 4; q++) {
                const int u = (m2 * 4 + q) ^ rx;
                float4 w4 = *(float4*)(Ab + r * 32 + u * 4);
                w4.x *= rz; w4.y *= rz; w4.z *= rz; w4.w *= rz;
                *(float4*)(Ab + r * 32 + u * 4) = w4;
            }
            __syncthreads();
        }

#pragma unroll
        for (int kk = 0; kk < 4; kk++) {
            const int u0 = (2 * kk) ^ g;
            const int u1 = u0 ^ 1;
            uint32_t af[2][4];
#pragma unroll
            for (int mt = 0; mt < 2; mt++) {
                const int ra = wm * 32 + mt * 16 + g;
                af[mt][0] = __float_as_uint(Ab[(ra)     * 32 + u0 * 4 + t4]);
                af[mt][1] = __float_as_uint(Ab[(ra + 8) * 32 + u0 * 4 + t4]);
                af[mt][2] = __float_as_uint(Ab[(ra)     * 32 + u1 * 4 + t4]);
                af[mt][3] = __float_as_uint(Ab[(ra + 8) * 32 + u1 * 4 + t4]);
            }
#pragma unroll
            for (int nt = 0; nt < 8; nt++) {
                const int rb = wn * 64 + nt * 8 + g;
                uint32_t b0 = __float_as_uint(Bb[rb * 32 + u0 * 4 + t4]);
                uint32_t b1 = __float_as_uint(Bb[rb * 32 + u1 * 4 + t4]);
#pragma unroll
                for (int mt = 0; mt < 2; mt++)
                    mma_tf32(acc[mt][nt][0], acc[mt][nt][1], acc[mt][nt][2], acc[mt][nt][3],
                             af[mt][0], af[mt][1], af[mt][2], af[mt][3], b0, b1);
            }
        }
        __syncthreads();
    }

    // =================== epilogues ===================
    if constexpr (EPI == 1) {
        // scores: e = exp(scale*acc), stage in smem, coalesced store + partials
        float* et = sm;   // 128 x 132 floats = 67.6KB (stage buffers are free now)
#pragma unroll
        for (int mt = 0; mt < 2; mt++) {
            const int lr = wm * 32 + mt * 16 + g;
#pragma unroll
            for (int nt = 0; nt < 8; nt++) {
                const int lc = wn * 64 + nt * 8 + t4 * 2;
                float e0 = __expf(acc[mt][nt][0] * scale);
                float e1 = __expf(acc[mt][nt][1] * scale);
                float e2 = __expf(acc[mt][nt][2] * scale);
                float e3 = __expf(acc[mt][nt][3] * scale);
                *(float2*)(et + (lr)     * 132 + lc) = make_float2(e0, e1);
                *(float2*)(et + (lr + 8) * 132 + lc) = make_float2(e2, e3);
            }
        }
        __syncthreads();
        // coalesced e-tile store
#pragma unroll
        for (int i = 0; i < 16; i++) {
            const int u = i * 256 + t;            // 0..4095
            const int r = u >> 5, c4 = u & 31;
            float4 v4 = *(float4*)(et + r * 132 + c4 * 4);
            *(float4*)(Co + (long)bz * sC + (long)(m0 + r) * ldc + n0 + c4 * 4) = v4;
        }
        // deterministic per-CTA partial sums over this tile's 8 key-L values
#pragma unroll
        for (int i = 0; i < 8; i++) {
            const int pr = i * 256 + t;           // 0..2047
            const int lr = pr >> 4, gg = pr & 15;
            float s8 = 0.f;
#pragma unroll
            for (int j = 0; j < 8; j++) s8 += et[lr * 132 + gg + 16 * j];
            PS[((long)(bz * 8 + blockIdx.x) * PP + m0 + lr) * 16 + gg] = s8;
        }
        return;
    }

    auto outoff = [&](int m, int n) -> long {
        if constexpr (OUTMAP == 0) {
            return (long)bz * sC + (long)m * ldc + n;
        } else if constexpr (OUTMAP == 1) {
            int b = m >> 10, p = m & 1023;
            int cq = n >> 3, h = n & 7;
            return (((long)(b * HH + h) * PP + p) << 7) + cq;
        } else if constexpr (OUTMAP == 2) {
            int b = bz >> 3, h = bz & 7;
            return ((long)(b * PP + m) << 10) + (n << 3) + h;
        } else {
            int b = m >> 10, p = m & 1023;
            int cq = n >> 3, h = n & 7;
            return (((long)(b * HH + h) * CC + cq) << 10) + p;
        }
    };

#pragma unroll
    for (int mt = 0; mt < 2; mt++) {
        const int r0 = m0 + wm * 32 + mt * 16 + g;
#pragma unroll
        for (int nt = 0; nt < 8; nt++) {
            const int col = n0 + wn * 64 + nt * 8 + t4 * 2;
            float v0 = acc[mt][nt][0] * scale;
            float v1 = acc[mt][nt][1] * scale;
            float v2 = acc[mt][nt][2] * scale;
            float v3 = acc[mt][nt][3] * scale;
            if (bias) {
                float bi0 = bias[col], bi1 = bias[col + 1];
                v0 += bi0; v1 += bi1; v2 += bi0; v3 += bi1;
            }
            if (RELU) {
                v0 = fmaxf(v0, 0.f); v1 = fmaxf(v1, 0.f);
                v2 = fmaxf(v2, 0.f); v3 = fmaxf(v3, 0.f);
            }
            if constexpr (OUTMAP == 0) {
                *(float2*)(Co + outoff(r0, col))     = make_float2(v0, v1);
                *(float2*)(Co + outoff(r0 + 8, col)) = make_float2(v2, v3);
            } else {
                Co[outoff(r0, col)]         = v0;
                Co[outoff(r0, col + 1)]     = v1;
                Co[outoff(r0 + 8, col)]     = v2;
                Co[outoff(r0 + 8, col + 1)] = v3;
            }
        }
    }
}

// ---------------------------------------------------------------------------
// out = LayerNorm(A + R) * gamma + beta
// ---------------------------------------------------------------------------
__global__ __launch_bounds__(128) void add_ln_kernel(
    const float* __restrict__ A, const float* __restrict__ R,
    const float* __restrict__ gam, const float* __restrict__ bet,
    float* __restrict__ out)
{
    const long base = (long)blockIdx.x * CC;
    const int t = threadIdx.x;
    __shared__ float red[8];

    float v = A[base + t] + R[base + t];

    float s = v;
#pragma unroll
    for (int o = 16; o; o >>= 1) s += __shfl_xor_sync(0xffffffffu, s, o);
    if ((t & 31) == 0) red[t >> 5] = s;
    __syncthreads();
    const float mean = (red[0] + red[1] + red[2] + red[3]) * (1.f / CC);

    const float d = v - mean;
    float s2 = d * d;
#pragma unroll
    for (int o = 16; o; o >>= 1) s2 += __shfl_xor_sync(0xffffffffu, s2, o);
    if ((t & 31) == 0) red[4 + (t >> 5)] = s2;
    __syncthreads();
    const float var = (red[4] + red[5] + red[6] + red[7]) * (1.f / CC);

    out[base + t] = d * rsqrtf(var + 1e-5f) * gam[t] + bet[t];
}

// ---------------------------------------------------------------------------
extern "C" void kernel_launch(void* const* d_in, const int* in_sizes, int n_in,
                              void* d_out, int out_size)
{
    const float* x     = (const float*)d_in[0];
    const float* wq    = (const float*)d_in[1];
    const float* bq    = (const float*)d_in[2];
    const float* wk    = (const float*)d_in[3];
    const float* bk    = (const float*)d_in[4];
    const float* wv    = (const float*)d_in[5];
    const float* bv    = (const float*)d_in[6];
    const float* wo    = (const float*)d_in[7];
    const float* bo    = (const float*)d_in[8];
    const float* ln1_g = (const float*)d_in[9];
    const float* ln1_b = (const float*)d_in[10];
    const float* w1    = (const float*)d_in[11];
    const float* b1    = (const float*)d_in[12];
    const float* w2    = (const float*)d_in[13];
    const float* b2    = (const float*)d_in[14];
    const float* ln2_g = (const float*)d_in[15];
    const float* ln2_b = (const float*)d_in[16];
    float* out = (float*)d_out;

    float* scr = nullptr;
    cudaGetSymbolAddress((void**)&scr, g_scratch);
    float* q   = scr + OFF_Q;
    float* k   = scr + OFF_K;
    float* vt  = scr + OFF_V;
    float* sS  = scr + OFF_S;
    float* zc  = scr + OFF_ZC;
    float* ao  = scr + OFF_AO;
    float* z1  = scr + OFF_Z1;
    float* h1  = scr + OFF_H1;
    float* ffy = scr + OFF_FFY;
    float* ps  = scr + OFF_PS;

    cudaFuncSetAttribute((const void*)tgemm<0, false, 0, false>, cudaFuncAttributeMaxDynamicSharedMemorySize, SMEM_BYTES);
    cudaFuncSetAttribute((const void*)tgemm<0, true,  0, false>, cudaFuncAttributeMaxDynamicSharedMemorySize, SMEM_BYTES);
    cudaFuncSetAttribute((const void*)tgemm<1, false, 0, false>, cudaFuncAttributeMaxDynamicSharedMemorySize, SMEM_BYTES);
    cudaFuncSetAttribute((const void*)tgemm<3, false, 0, false>, cudaFuncAttributeMaxDynamicSharedMemorySize, SMEM_BYTES);
    cudaFuncSetAttribute((const void*)tgemm<0, false, 1, false>, cudaFuncAttributeMaxDynamicSharedMemorySize, SMEM_BYTES);
    cudaFuncSetAttribute((const void*)tgemm<2, false, 0, true>,  cudaFuncAttributeMaxDynamicSharedMemorySize, SMEM_AV_BYTES);

    const float inv_sqrt_c = 0.08838834764831845f;

    // 1-3: QKV projections (8192 x 1024 x 128)
    tgemm<1, false, 0, false><<<dim3(8, 64, 1), 256, SMEM_BYTES>>>(
        x, CC, 0, wq, CC, 0, bq, q, 0, 0, CC, 1.f, nullptr);
    tgemm<1, false, 0, false><<<dim3(8, 64, 1), 256, SMEM_BYTES>>>(
        x, CC, 0, wk, CC, 0, bk, k, 0, 0, CC, 1.f, nullptr);
    tgemm<3, false, 0, false><<<dim3(8, 64, 1), 256, SMEM_BYTES>>>(
        x, CC, 0, wv, CC, 0, bv, vt, 0, 0, CC, 1.f, nullptr);

    // 4: e = exp(Q @ K^T / sqrt(C)) + per-CTA key-L partial sums -> PS
    tgemm<0, false, 1, false><<<dim3(8, 8, 64), 256, SMEM_BYTES>>>(
        q, CC, (long)PP * CC, k, CC, (long)PP * CC, nullptr,
        sS, PP, (long)PP * PP, CC, inv_sqrt_c, ps);

    // 5: Z = softmax2(e) @ Vt^T (normalization fused into A-chunk transform)
    tgemm<2, false, 0, true><<<dim3(1, 8, 64), 256, SMEM_AV_BYTES>>>(
        sS, PP, (long)PP * PP, vt, PP, (long)CC * PP, nullptr,
        zc, 0, 0, PP, 1.f, ps);

    // 6: attn_out = zc @ wo^T + bo  (8192x128x1024)
    tgemm<0, false, 0, false><<<dim3(1, 64, 1), 256, SMEM_BYTES>>>(
        zc, CH, 0, wo, CH, 0, bo, ao, CC, 0, CH, 1.f, nullptr);

    // 7: z1 = LN1(attn_out + x)
    add_ln_kernel<<<NTOK, 128>>>(ao, x, ln1_g, ln1_b, z1);

    // 8: h1 = relu(z1 @ w1^T + b1)  (8192x512x128)
    tgemm<0, true, 0, false><<<dim3(4, 64, 1), 256, SMEM_BYTES>>>(
        z1, CC, 0, w1, CC, 0, b1, h1, FFN, 0, CC, 1.f, nullptr);

    // 9: ffy = h1 @ w2^T + b2  (8192x128x512)
    tgemm<0, false, 0, false><<<dim3(1, 64, 1), 256, SMEM_BYTES>>>(
        h1, FFN, 0, w2, FFN, 0, b2, ffy, CC, 0, FFN, 1.f, nullptr);

    // 10: out = LN2(ffy + z1)
    add_ln_kernel<<<NTOK, 128>>>(ffy, z1, ln2_g, ln2_b, out);
}

// round 17
// speedup vs baseline: 1.3642x; 1.0135x over previous
#include <cuda_runtime.h>
#include <cuda_bf16.h>
#include <cstdint>
#include <math.h>

// Problem constants
#define BB 8
#define CC 128
#define HH 8
#define FFN 512
#define PP 1024            // L*F positions per batch
#define NTOK 8192          // B*P tokens
#define CH 1024            // C*H

// ---------------------------------------------------------------------------
// Scratch (float units; the e-tensor region holds bf16 now, still fits)
// ---------------------------------------------------------------------------
#define OFF_Q   0L
#define SZ_QKV  (8L * 8 * 1024 * 128)
#define OFF_K   (OFF_Q + SZ_QKV)
#define OFF_V   (OFF_K + SZ_QKV)           // V stored TRANSPOSED: (bh, c, p)
#define OFF_S   (OFF_V + SZ_QKV)
#define SZ_S    (64L * 1024 * 1024)
#define OFF_ZC  (OFF_S + SZ_S)
#define SZ_ZC   (8192L * 1024)
#define OFF_AO  (OFF_ZC + SZ_ZC)
#define SZ_TOK  (8192L * 128)
#define OFF_Z1  (OFF_AO + SZ_TOK)
#define OFF_H1  (OFF_Z1 + SZ_TOK)
#define SZ_H1   (8192L * 512)
#define OFF_FFY (OFF_H1 + SZ_H1)
#define OFF_PS  (OFF_FFY + SZ_TOK)
#define SZ_PS   (64L * 8 * 1024 * 16)      // [bh][ntile][row][g] partial exp-sums
#define SCRATCH_TOTAL (OFF_PS + SZ_PS)

__device__ float g_scratch[SCRATCH_TOTAL];

// ---------------------------------------------------------------------------
// PTX helpers
// ---------------------------------------------------------------------------
__device__ __forceinline__ void mma_tf32(
    float& c0, float& c1, float& c2, float& c3,
    uint32_t a0, uint32_t a1, uint32_t a2, uint32_t a3,
    uint32_t b0, uint32_t b1)
{
    asm volatile(
        "mma.sync.aligned.m16n8k8.row.col.f32.tf32.tf32.f32 "
        "{%0,%1,%2,%3}, {%4,%5,%6,%7}, {%8,%9}, {%0,%1,%2,%3};"
        : "+f"(c0), "+f"(c1), "+f"(c2), "+f"(c3)
        : "r"(a0), "r"(a1), "r"(a2), "r"(a3), "r"(b0), "r"(b1));
}

__device__ __forceinline__ uint32_t smem_u32(const void* p) {
    uint32_t a;
    asm("{ .reg .u64 t; cvta.to.shared.u64 t, %1; cvt.u32.u64 %0, t; }" : "=r"(a) : "l"(p));
    return a;
}
__device__ __forceinline__ void cp16(uint32_t dst, const void* src) {
    asm volatile("cp.async.cg.shared.global [%0], [%1], 16;" :: "r"(dst), "l"(src));
}
__device__ __forceinline__ void cp_commit() {
    asm volatile("cp.async.commit_group;" ::: "memory");
}
template<int N>
__device__ __forceinline__ void cp_wait() {
    asm volatile("cp.async.wait_group %0;" :: "n"(N) : "memory");
}

__device__ __forceinline__ uint32_t pack_bf(float a, float b) {
    uint16_t la = __bfloat16_as_ushort(__float2bfloat16(a));
    uint16_t lb = __bfloat16_as_ushort(__float2bfloat16(b));
    return (uint32_t)la | ((uint32_t)lb << 16);
}
__device__ __forceinline__ float2 bf2f2(uint32_t u) {
    __nv_bfloat162 h = *reinterpret_cast<__nv_bfloat162*>(&u);
    return __bfloat1622float2(h);   // .x = low half = lower address
}

// ===========================================================================
// TF32 tensor-core GEMM, 128x128 tile, cp.async 3-stage pipeline.
// EPI 0: normal (scale/bias/relu + OUTMAP store)
// EPI 1: scores: e = bf16round(exp(scale*acc)); bf16 store + PS partial sums
// SMAXA: A operand is the bf16 e-tensor; per-chunk double-softmax
//        normalization into fp32 transform buffer Tb, mma reads Tb.
// ===========================================================================
template<int OUTMAP, bool RELU, int EPI, bool SMAXA>
__global__ __launch_bounds__(256, 2) void tgemm(
    const float* __restrict__ A, int lda, long sA,   // SMAXA: bf16 elements
    const float* __restrict__ Bm, int ldb, long sB,
    const float* __restrict__ bias,
    float* __restrict__ Co, int ldc, long sC,
    int K, float scale, float* __restrict__ PS)
{
    constexpr int STB  = SMAXA ? 24576 : 32768;   // stage bytes
    constexpr int BOFF = SMAXA ? 8192  : 16384;   // B tile offset within stage

    extern __shared__ float sm[];
    const uint32_t sbase = smem_u32(sm);
    float* Tb   = sm + (3 * STB) / 4;             // 16KB fp32 transform buf (SMAXA)
    float* invs = Tb + 4096;                      // 128 x 20 fp32 (SMAXA)

    const int t   = threadIdx.x;
    const int wid = t >> 5;
    const int lid = t & 31;
    const int g   = lid >> 2;
    const int t4  = lid & 3;
    const int wm  = wid & 3;
    const int wn  = wid >> 2;

    const int bz = blockIdx.z;
    const int m0 = blockIdx.y << 7;
    const int n0 = blockIdx.x << 7;

    const __nv_bfloat16* A16 =
        reinterpret_cast<const __nv_bfloat16*>(A) + (SMAXA ? (long)bz * sA : 0);
    if constexpr (!SMAXA) A += (long)bz * sA;
    Bm += (long)bz * sB;

    const int r_ld  = t >> 3;
    const int c4_ld = t & 7;

    auto issue_stage = [&](int c, int s) {
        const int k0 = c << 5;
        const uint32_t stage = sbase + s * STB;
        if constexpr (SMAXA) {
#pragma unroll
            for (int i = 0; i < 2; i++) {
                int u = i * 256 + t;          // 0..511
                int r = u >> 2, c2 = u & 3;
                cp16(stage + r * 64 + c2 * 16,
                     A16 + (long)(m0 + r) * lda + k0 + c2 * 8);
            }
        } else {
#pragma unroll
            for (int i = 0; i < 4; i++) {
                const int r  = r_ld + i * 32;
                const uint32_t doff = (uint32_t)(r << 7) + (uint32_t)((c4_ld ^ (r & 7)) << 4);
                cp16(stage + doff, A + (long)(m0 + r) * lda + k0 + (c4_ld << 2));
            }
        }
#pragma unroll
        for (int i = 0; i < 4; i++) {
            const int r  = r_ld + i * 32;
            const uint32_t doff = (uint32_t)(r << 7) + (uint32_t)((c4_ld ^ (r & 7)) << 4);
            cp16(stage + BOFF + doff, Bm + (long)(n0 + r) * ldb + k0 + (c4_ld << 2));
        }
        cp_commit();
    };

    float acc[2][8][4];
#pragma unroll
    for (int mt = 0; mt < 2; mt++)
#pragma unroll
        for (int nt = 0; nt < 8; nt++)
#pragma unroll
            for (int i = 0; i < 4; i++) acc[mt][nt][i] = 0.f;

    const int nch = K >> 5;

    // prologue: fill first 2 stages
    if (0 < nch) issue_stage(0, 0);
    if (1 < nch) issue_stage(1, 1);

    // ---- SMAXA: build inv_sum1[row][g] (stride 20) ----
    if constexpr (SMAXA) {
#pragma unroll
        for (int i = 0; i < 8; i++) {
            const int pr = i * 256 + t;          // 0..2047
            const int lr = pr >> 4, gg = pr & 15;
            float s1 = 0.f;
#pragma unroll
            for (int nx = 0; nx < 8; nx++)
                s1 += PS[((long)(bz * 8 + nx) * PP + m0 + lr) * 16 + gg];
            invs[lr * 20 + gg] = 1.0f / s1;
        }
        __syncthreads();
    }

    for (int c = 0; c < nch; c++) {
        const int s = c % 3;
        cp_wait<1>();
        __syncthreads();

        if (c + 2 < nch) issue_stage(c + 2, (c + 2) % 3);

        float* Ab;
        const float* Bb = sm + s * (STB / 4) + BOFF / 4;

        if constexpr (SMAXA) {
            // transform bf16 e-chunk -> normalized fp32 in Tb
            const int r  = t >> 1;
            const int m2 = t & 1;
            const int rx = r & 7;
            const uint32_t* Ain = reinterpret_cast<const uint32_t*>(sm) +
                                  s * (STB / 4) + r * 16 + m2 * 8;
            float z = 0.f;
#pragma unroll
            for (int q = 0; q < 4; q++) {
                float2 p0 = bf2f2(Ain[q * 2]);
                float2 p1 = bf2f2(Ain[q * 2 + 1]);
                float4 iv = *(float4*)(invs + r * 20 + q * 4);
                float w0 = __expf(p0.x * iv.x);
                float w1 = __expf(p0.y * iv.y);
                float w2 = __expf(p1.x * iv.z);
                float w3 = __expf(p1.y * iv.w);
                z += (w0 + w1) + (w2 + w3);
                const int u = (m2 * 4 + q) ^ rx;
                *(float4*)(Tb + r * 32 + u * 4) = make_float4(w0, w1, w2, w3);
            }
            const float rz = 1.0f / z;
#pragma unroll
            for (int q = 0; q < 4; q++) {
                const int u = (m2 * 4 + q) ^ rx;
                float4 w4 = *(float4*)(Tb + r * 32 + u * 4);
                w4.x *= rz; w4.y *= rz; w4.z *= rz; w4.w *= rz;
                *(float4*)(Tb + r * 32 + u * 4) = w4;
            }
            __syncthreads();
            Ab = Tb;
        } else {
            Ab = sm + s * (STB / 4);
        }

#pragma unroll
        for (int kk = 0; kk < 4; kk++) {
            const int u0 = (2 * kk) ^ g;
            const int u1 = u0 ^ 1;
            uint32_t af[2][4];
#pragma unroll
            for (int mt = 0; mt < 2; mt++) {
                const int ra = wm * 32 + mt * 16 + g;
                af[mt][0] = __float_as_uint(Ab[(ra)     * 32 + u0 * 4 + t4]);
                af[mt][1] = __float_as_uint(Ab[(ra + 8) * 32 + u0 * 4 + t4]);
                af[mt][2] = __float_as_uint(Ab[(ra)     * 32 + u1 * 4 + t4]);
                af[mt][3] = __float_as_uint(Ab[(ra + 8) * 32 + u1 * 4 + t4]);
            }
#pragma unroll
            for (int nt = 0; nt < 8; nt++) {
                const int rb = wn * 64 + nt * 8 + g;
                uint32_t b0 = __float_as_uint(Bb[rb * 32 + u0 * 4 + t4]);
                uint32_t b1 = __float_as_uint(Bb[rb * 32 + u1 * 4 + t4]);
#pragma unroll
                for (int mt = 0; mt < 2; mt++)
                    mma_tf32(acc[mt][nt][0], acc[mt][nt][1], acc[mt][nt][2], acc[mt][nt][3],
                             af[mt][0], af[mt][1], af[mt][2], af[mt][3], b0, b1);
            }
        }
        __syncthreads();
    }

    // =================== epilogues ===================
    if constexpr (EPI == 1) {
        // scores: e = bf16round(exp(scale*acc)); smem stage; bf16 store + PS
        float* et = sm;   // 128 x 132 fp32
#pragma unroll
        for (int mt = 0; mt < 2; mt++) {
            const int lr = wm * 32 + mt * 16 + g;
#pragma unroll
            for (int nt = 0; nt < 8; nt++) {
                const int lc = wn * 64 + nt * 8 + t4 * 2;
                float e0 = __bfloat162float(__float2bfloat16(__expf(acc[mt][nt][0] * scale)));
                float e1 = __bfloat162float(__float2bfloat16(__expf(acc[mt][nt][1] * scale)));
                float e2 = __bfloat162float(__float2bfloat16(__expf(acc[mt][nt][2] * scale)));
                float e3 = __bfloat162float(__float2bfloat16(__expf(acc[mt][nt][3] * scale)));
                *(float2*)(et + (lr)     * 132 + lc) = make_float2(e0, e1);
                *(float2*)(et + (lr + 8) * 132 + lc) = make_float2(e2, e3);
            }
        }
        __syncthreads();
        // coalesced bf16 store: 8 bf16 (16B) per thread-iteration
        __nv_bfloat16* Cob = reinterpret_cast<__nv_bfloat16*>(Co);
#pragma unroll
        for (int i = 0; i < 8; i++) {
            const int u = i * 256 + t;            // 0..2047
            const int r = u >> 4, c8 = u & 15;
            float4 a4 = *(float4*)(et + r * 132 + c8 * 8);
            float4 b4 = *(float4*)(et + r * 132 + c8 * 8 + 4);
            uint4 o;
            o.x = pack_bf(a4.x, a4.y);
            o.y = pack_bf(a4.z, a4.w);
            o.z = pack_bf(b4.x, b4.y);
            o.w = pack_bf(b4.z, b4.w);
            *(uint4*)(Cob + (long)bz * sC + (long)(m0 + r) * ldc + n0 + c8 * 8) = o;
        }
        // deterministic per-CTA partial sums (from rounded values)
#pragma unroll
        for (int i = 0; i < 8; i++) {
            const int pr = i * 256 + t;           // 0..2047
            const int lr = pr >> 4, gg = pr & 15;
            float s8 = 0.f;
#pragma unroll
            for (int j = 0; j < 8; j++) s8 += et[lr * 132 + gg + 16 * j];
            PS[((long)(bz * 8 + blockIdx.x) * PP + m0 + lr) * 16 + gg] = s8;
        }
        return;
    }

    auto outoff = [&](int m, int n) -> long {
        if constexpr (OUTMAP == 0) {
            return (long)bz * sC + (long)m * ldc + n;
        } else if constexpr (OUTMAP == 1) {
            int b = m >> 10, p = m & 1023;
            int cq = n >> 3, h = n & 7;
            return (((long)(b * HH + h) * PP + p) << 7) + cq;
        } else if constexpr (OUTMAP == 2) {
            int b = bz >> 3, h = bz & 7;
            return ((long)(b * PP + m) << 10) + (n << 3) + h;
        } else {
            int b = m >> 10, p = m & 1023;
            int cq = n >> 3, h = n & 7;
            return (((long)(b * HH + h) * CC + cq) << 10) + p;
        }
    };

#pragma unroll
    for (int mt = 0; mt < 2; mt++) {
        const int r0 = m0 + wm * 32 + mt * 16 + g;
#pragma unroll
        for (int nt = 0; nt < 8; nt++) {
            const int col = n0 + wn * 64 + nt * 8 + t4 * 2;
            float v0 = acc[mt][nt][0] * scale;
            float v1 = acc[mt][nt][1] * scale;
            float v2 = acc[mt][nt][2] * scale;
            float v3 = acc[mt][nt][3] * scale;
            if (bias) {
                float bi0 = bias[col], bi1 = bias[col + 1];
                v0 += bi0; v1 += bi1; v2 += bi0; v3 += bi1;
            }
            if (RELU) {
                v0 = fmaxf(v0, 0.f); v1 = fmaxf(v1, 0.f);
                v2 = fmaxf(v2, 0.f); v3 = fmaxf(v3, 0.f);
            }
            if constexpr (OUTMAP == 0) {
                *(float2*)(Co + outoff(r0, col))     = make_float2(v0, v1);
                *(float2*)(Co + outoff(r0 + 8, col)) = make_float2(v2, v3);
            } else {
                Co[outoff(r0, col)]         = v0;
                Co[outoff(r0, col + 1)]     = v1;
                Co[outoff(r0 + 8, col)]     = v2;
                Co[outoff(r0 + 8, col + 1)] = v3;
            }
        }
    }
}

// smem sizes
#define SMEM_BYTES    98304                       // 3 * 32768
#define SMEM_AV_BYTES (3 * 24576 + 16384 + 10240) // 100352

// ---------------------------------------------------------------------------
// out = LayerNorm(A + R) * gamma + beta
// ---------------------------------------------------------------------------
__global__ __launch_bounds__(128) void add_ln_kernel(
    const float* __restrict__ A, const float* __restrict__ R,
    const float* __restrict__ gam, const float* __restrict__ bet,
    float* __restrict__ out)
{
    const long base = (long)blockIdx.x * CC;
    const int t = threadIdx.x;
    __shared__ float red[8];

    float v = A[base + t] + R[base + t];

    float s = v;
#pragma unroll
    for (int o = 16; o; o >>= 1) s += __shfl_xor_sync(0xffffffffu, s, o);
    if ((t & 31) == 0) red[t >> 5] = s;
    __syncthreads();
    const float mean = (red[0] + red[1] + red[2] + red[3]) * (1.f / CC);

    const float d = v - mean;
    float s2 = d * d;
#pragma unroll
    for (int o = 16; o; o >>= 1) s2 += __shfl_xor_sync(0xffffffffu, s2, o);
    if ((t & 31) == 0) red[4 + (t >> 5)] = s2;
    __syncthreads();
    const float var = (red[4] + red[5] + red[6] + red[7]) * (1.f / CC);

    out[base + t] = d * rsqrtf(var + 1e-5f) * gam[t] + bet[t];
}

// ---------------------------------------------------------------------------
extern "C" void kernel_launch(void* const* d_in, const int* in_sizes, int n_in,
                              void* d_out, int out_size)
{
    const float* x     = (const float*)d_in[0];
    const float* wq    = (const float*)d_in[1];
    const float* bq    = (const float*)d_in[2];
    const float* wk    = (const float*)d_in[3];
    const float* bk    = (const float*)d_in[4];
    const float* wv    = (const float*)d_in[5];
    const float* bv    = (const float*)d_in[6];
    const float* wo    = (const float*)d_in[7];
    const float* bo    = (const float*)d_in[8];
    const float* ln1_g = (const float*)d_in[9];
    const float* ln1_b = (const float*)d_in[10];
    const float* w1    = (const float*)d_in[11];
    const float* b1    = (const float*)d_in[12];
    const float* w2    = (const float*)d_in[13];
    const float* b2    = (const float*)d_in[14];
    const float* ln2_g = (const float*)d_in[15];
    const float* ln2_b = (const float*)d_in[16];
    float* out = (float*)d_out;

    float* scr = nullptr;
    cudaGetSymbolAddress((void**)&scr, g_scratch);
    float* q   = scr + OFF_Q;
    float* k   = scr + OFF_K;
    float* vt  = scr + OFF_V;
    float* sS  = scr + OFF_S;     // holds bf16 e-tensor now
    float* zc  = scr + OFF_ZC;
    float* ao  = scr + OFF_AO;
    float* z1  = scr + OFF_Z1;
    float* h1  = scr + OFF_H1;
    float* ffy = scr + OFF_FFY;
    float* ps  = scr + OFF_PS;

    cudaFuncSetAttribute((const void*)tgemm<0, false, 0, false>, cudaFuncAttributeMaxDynamicSharedMemorySize, SMEM_BYTES);
    cudaFuncSetAttribute((const void*)tgemm<0, true,  0, false>, cudaFuncAttributeMaxDynamicSharedMemorySize, SMEM_BYTES);
    cudaFuncSetAttribute((const void*)tgemm<1, false, 0, false>, cudaFuncAttributeMaxDynamicSharedMemorySize, SMEM_BYTES);
    cudaFuncSetAttribute((const void*)tgemm<3, false, 0, false>, cudaFuncAttributeMaxDynamicSharedMemorySize, SMEM_BYTES);
    cudaFuncSetAttribute((const void*)tgemm<0, false, 1, false>, cudaFuncAttributeMaxDynamicSharedMemorySize, SMEM_BYTES);
    cudaFuncSetAttribute((const void*)tgemm<2, false, 0, true>,  cudaFuncAttributeMaxDynamicSharedMemorySize, SMEM_AV_BYTES);

    const float inv_sqrt_c = 0.08838834764831845f;

    // 1-3: QKV projections (8192 x 1024 x 128)
    tgemm<1, false, 0, false><<<dim3(8, 64, 1), 256, SMEM_BYTES>>>(
        x, CC, 0, wq, CC, 0, bq, q, 0, 0, CC, 1.f, nullptr);
    tgemm<1, false, 0, false><<<dim3(8, 64, 1), 256, SMEM_BYTES>>>(
        x, CC, 0, wk, CC, 0, bk, k, 0, 0, CC, 1.f, nullptr);
    tgemm<3, false, 0, false><<<dim3(8, 64, 1), 256, SMEM_BYTES>>>(
        x, CC, 0, wv, CC, 0, bv, vt, 0, 0, CC, 1.f, nullptr);

    // 4: e = bf16(exp(Q @ K^T / sqrt(C))) + per-CTA key-L partial sums -> PS
    tgemm<0, false, 1, false><<<dim3(8, 8, 64), 256, SMEM_BYTES>>>(
        q, CC, (long)PP * CC, k, CC, (long)PP * CC, nullptr,
        sS, PP, (long)PP * PP, CC, inv_sqrt_c, ps);

    // 5: Z = softmax2(e) @ Vt^T (normalization fused; A streamed as bf16)
    tgemm<2, false, 0, true><<<dim3(1, 8, 64), 256, SMEM_AV_BYTES>>>(
        sS, PP, (long)PP * PP, vt, PP, (long)CC * PP, nullptr,
        zc, 0, 0, PP, 1.f, ps);

    // 6: attn_out = zc @ wo^T + bo  (8192x128x1024)
    tgemm<0, false, 0, false><<<dim3(1, 64, 1), 256, SMEM_BYTES>>>(
        zc, CH, 0, wo, CH, 0, bo, ao, CC, 0, CH, 1.f, nullptr);

    // 7: z1 = LN1(attn_out + x)
    add_ln_kernel<<<NTOK, 128>>>(ao, x, ln1_g, ln1_b, z1);

    // 8: h1 = relu(z1 @ w1^T + b1)  (8192x512x128)
    tgemm<0, true, 0, false><<<dim3(4, 64, 1), 256, SMEM_BYTES>>>(
        z1, CC, 0, w1, CC, 0, b1, h1, FFN, 0, CC, 1.f, nullptr);

    // 9: ffy = h1 @ w2^T + b2  (8192x128x512)
    tgemm<0, false, 0, false><<<dim3(1, 64, 1), 256, SMEM_BYTES>>>(
        h1, FFN, 0, w2, FFN, 0, b2, ffy, CC, 0, FFN, 1.f, nullptr);

    // 10: out = LN2(ffy + z1)
    add_ln_kernel<<<NTOK, 128>>>(ffy, z1, ln2_g, ln2_b, out);
}